// round 11
// baseline (speedup 1.0000x reference)
#include <cuda_runtime.h>
#include <cuda_bf16.h>
#include <cstdint>

// Problem constants (B=4, S=2048, D=16, HEADS=16, HEAD_SIZE=1)
#define BB   4
#define SS   2048
#define DD   16
#define NPAIR (BB * DD)          // 64 (b,h) pairs
#define HALF (SS / 2)            // 1024 rows per sub-block
#define NC   23                  // polynomial coefficients (degree 22)

// Scratch (allocation-free rule: __device__ global)
__device__ float g_att[BB * SS * DD];   // [b][s][h]

// ---------------------------------------------------------------------------
// Kernel 1: fused QKV + polynomial causal softmax-attention.
// grid 128 = 64 pairs x 2 sub-blocks (one block per SM), 512 threads.
// Scalar-head trick: e^{q k} = sum_p q^p/p! k^p is separable; causal attention
// = prefix sums of moments M_p[i] = sum_{j<=i} k_j^p (v_j).
// sub=0 scans rows [0,1024); sub=1 redundantly REDUCES first-half totals from
// x, then scans rows [1024,2048). Register-resident; 2 rows/thread; warp
// shfl-scan + warp-carry. att written to g_att[b][s][h] (plain stores).
// ---------------------------------------------------------------------------
__global__ void __launch_bounds__(512) attn_poly_kernel(
    const float* __restrict__ x,      // [B, S, D]
    const float* __restrict__ w,      // [16, 48] row-major
    const float* __restrict__ bias,   // [48]
    float* __restrict__ gatt)         // [b][s][h]
{
    __shared__ float swq[DD], swk[DD], swv[DD];
    __shared__ float sb3[3];
    __shared__ float sWT[16][NC + 1];     // warp totals / pre-reduce scratch
    __shared__ float sWC[16][NC + 1];     // warp exclusive carries
    __shared__ float sbase[NC + 1];       // first-half totals (sub=1)

    const float INVF[NC] = {
        1.0f, 1.0f, 0.5f, 1.6666667e-1f, 4.1666668e-2f, 8.3333338e-3f,
        1.3888889e-3f, 1.9841270e-4f, 2.4801588e-5f, 2.7557319e-6f,
        2.7557319e-7f, 2.5052108e-8f, 2.0876757e-9f, 1.6059044e-10f,
        1.1470746e-11f, 7.6471637e-13f, 4.7794773e-14f, 2.8114573e-15f,
        1.5619207e-16f, 8.2206352e-18f, 4.1103176e-19f, 1.9572941e-20f,
        8.8967914e-22f };

    int bid  = blockIdx.x;
    int pair = bid >> 1;
    int sub  = bid & 1;
    int b_idx = pair >> 4;
    int h_idx = pair & 15;
    int t = threadIdx.x, lane = t & 31, wrp = t >> 5;

    if (t < DD) {
        swq[t] = w[t * 48 + h_idx];
        swk[t] = w[t * 48 + 16 + h_idx];
        swv[t] = w[t * 48 + 32 + h_idx];
    }
    if (t < 3) sb3[t] = bias[t * 16 + h_idx];
    __syncthreads();

    float bq = sb3[0], bk = sb3[1], bv = sb3[2];
    const float4* xb = reinterpret_cast<const float4*>(x + (size_t)b_idx * SS * DD);

    // --- own rows: r0 = base + 2t, r1 = r0 + 1 ---
    int base = sub * HALF;
    int r0 = base + 2 * t, r1 = r0 + 1;

    float q0, k0, v0, q1, k1, v1;
    {
        float xr[DD];
        #pragma unroll
        for (int q4 = 0; q4 < 4; q4++) {
            float4 t4 = xb[r0 * 4 + q4];
            xr[q4*4+0]=t4.x; xr[q4*4+1]=t4.y; xr[q4*4+2]=t4.z; xr[q4*4+3]=t4.w;
        }
        q0 = bq; k0 = bk; v0 = bv;
        #pragma unroll
        for (int d = 0; d < DD; d++) {
            q0 = fmaf(xr[d], swq[d], q0);
            k0 = fmaf(xr[d], swk[d], k0);
            v0 = fmaf(xr[d], swv[d], v0);
        }
        #pragma unroll
        for (int q4 = 0; q4 < 4; q4++) {
            float4 t4 = xb[r1 * 4 + q4];
            xr[q4*4+0]=t4.x; xr[q4*4+1]=t4.y; xr[q4*4+2]=t4.z; xr[q4*4+3]=t4.w;
        }
        q1 = bq; k1 = bk; v1 = bv;
        #pragma unroll
        for (int d = 0; d < DD; d++) {
            q1 = fmaf(xr[d], swq[d], q1);
            k1 = fmaf(xr[d], swk[d], k1);
            v1 = fmaf(xr[d], swv[d], v1);
        }
    }

    // --- pre rows (first half) for sub=1: k,v only ---
    float pk0 = 0.f, pv0 = 0.f, pk1 = 0.f, pv1 = 0.f;
    if (sub) {
        int p0 = 2 * t, p1 = p0 + 1;
        float xr[DD];
        #pragma unroll
        for (int q4 = 0; q4 < 4; q4++) {
            float4 t4 = xb[p0 * 4 + q4];
            xr[q4*4+0]=t4.x; xr[q4*4+1]=t4.y; xr[q4*4+2]=t4.z; xr[q4*4+3]=t4.w;
        }
        pk0 = bk; pv0 = bv;
        #pragma unroll
        for (int d = 0; d < DD; d++) {
            pk0 = fmaf(xr[d], swk[d], pk0);
            pv0 = fmaf(xr[d], swv[d], pv0);
        }
        #pragma unroll
        for (int q4 = 0; q4 < 4; q4++) {
            float4 t4 = xb[p1 * 4 + q4];
            xr[q4*4+0]=t4.x; xr[q4*4+1]=t4.y; xr[q4*4+2]=t4.z; xr[q4*4+3]=t4.w;
        }
        pk1 = bk; pv1 = bv;
        #pragma unroll
        for (int d = 0; d < DD; d++) {
            pk1 = fmaf(xr[d], swk[d], pk1);
            pv1 = fmaf(xr[d], swv[d], pv1);
        }
    }

    float den0, den1;            // this thread's two row denominators
    float* gout = gatt + (size_t)(b_idx * SS) * DD + h_idx;

    // ====================== two phases: 0 = den, 1 = num ======================
    #pragma unroll
    for (int phase = 0; phase < 2; phase++) {
        float m0 = phase ? v0 : 1.f;      // own-row moment weights
        float m1 = phase ? v1 : 1.f;
        float pm0 = phase ? pv0 : 1.f;    // pre-row moment weights
        float pm1 = phase ? pv1 : 1.f;

        // --- pre-half total reduction (sub=1 only; block-uniform branch) ---
        float pre[NC];
        if (sub) {
            float Tp[NC];
            {
                float kp = 1.f;
                #pragma unroll
                for (int p = 0; p < NC; p++) { Tp[p] = kp * pm0; kp *= pk0; }
                kp = 1.f;
                #pragma unroll
                for (int p = 0; p < NC; p++) { Tp[p] = fmaf(kp, pm1, Tp[p]); kp *= pk1; }
            }
            #pragma unroll
            for (int off = 16; off; off >>= 1)
                #pragma unroll
                for (int p = 0; p < NC; p++)
                    Tp[p] += __shfl_xor_sync(0xffffffffu, Tp[p], off);
            if (lane == 0)
                #pragma unroll
                for (int p = 0; p < NC; p++) sWT[wrp][p] = Tp[p];
            __syncthreads();
            if (wrp == 0 && lane < NC) {
                float s = 0.f;
                #pragma unroll
                for (int w16 = 0; w16 < 16; w16++) s += sWT[w16][lane];
                sbase[lane] = s;
            }
            __syncthreads();
            #pragma unroll
            for (int p = 0; p < NC; p++) pre[p] = sbase[p];
            __syncthreads();   // protect sbase/sWT before reuse below
        } else {
            #pragma unroll
            for (int p = 0; p < NC; p++) pre[p] = 0.f;
        }

        // --- serial moments of own 2 rows ---
        float T[NC];
        {
            float kp = 1.f;
            #pragma unroll
            for (int p = 0; p < NC; p++) { T[p] = kp * m0; kp *= k0; }
            kp = 1.f;
            #pragma unroll
            for (int p = 0; p < NC; p++) { T[p] = fmaf(kp, m1, T[p]); kp *= k1; }
        }

        // --- warp inclusive scan over lanes ---
        #pragma unroll
        for (int d = 1; d < 32; d <<= 1)
            #pragma unroll
            for (int p = 0; p < NC; p++) {
                float o = __shfl_up_sync(0xffffffffu, T[p], d);
                if (lane >= d) T[p] += o;
            }
        if (lane == 31)
            #pragma unroll
            for (int p = 0; p < NC; p++) sWT[wrp][p] = T[p];
        __syncthreads();
        if (wrp == 0 && lane < NC) {
            float c = 0.f;
            #pragma unroll
            for (int w16 = 0; w16 < 16; w16++) {
                float tot = sWT[w16][lane];
                sWC[w16][lane] = c;
                c += tot;
            }
        }
        __syncthreads();

        // --- exclusive prefix for this thread (before row r0) ---
        float A[NC];
        #pragma unroll
        for (int p = 0; p < NC; p++) {
            float o = __shfl_up_sync(0xffffffffu, T[p], 1);
            A[p] = pre[p] + sWC[wrp][p] + (lane ? o : 0.f);
        }
        __syncthreads();   // sWT/sWC reuse safety for next phase

        // --- passB: include own rows, evaluate polynomial ---
        {
            float kp = 1.f;
            #pragma unroll
            for (int p = 0; p < NC; p++) { A[p] = fmaf(kp, m0, A[p]); kp *= k0; }
            float qp = 1.f, acc = 0.f;
            #pragma unroll
            for (int p = 0; p < NC; p++) { acc = fmaf(A[p] * INVF[p], qp, acc); qp *= q0; }
            if (phase == 0) den0 = acc;
            else            gout[(size_t)r0 * DD] = acc / den0;

            kp = 1.f;
            #pragma unroll
            for (int p = 0; p < NC; p++) { A[p] = fmaf(kp, m1, A[p]); kp *= k1; }
            qp = 1.f; acc = 0.f;
            #pragma unroll
            for (int p = 0; p < NC; p++) { acc = fmaf(A[p] * INVF[p], qp, acc); qp *= q1; }
            if (phase == 0) den1 = acc;
            else            gout[(size_t)r1 * DD] = acc / den1;
        }
    }
}

// ---------------------------------------------------------------------------
// Kernel 2: out = att @ w_out + b_out.  One lane per output element:
// g = global thread id, row = g>>4, col = g&15. att[row][h] reads broadcast
// within 16-lane groups; w in SMEM. 512 blocks x 256 threads. Applies bias
// (no separate init kernel needed).
// ---------------------------------------------------------------------------
__global__ void __launch_bounds__(256) out_kernel(
    const float* __restrict__ gatt,
    const float* __restrict__ w,    // [16,16] row-major
    const float* __restrict__ bias, // [16]
    float* __restrict__ out)
{
    __shared__ float sw[DD * DD];
    __shared__ float sb[DD];
    int t = threadIdx.x;
    sw[t] = w[t];
    if (t < DD) sb[t] = bias[t];
    __syncthreads();

    int g = blockIdx.x * 256 + t;       // 0 .. 131071
    int r = g >> 4;                      // row 0..8191
    int d = g & 15;                      // output col

    const float* ar = gatt + (size_t)r * DD;
    float acc = sb[d];
    #pragma unroll
    for (int h = 0; h < DD; h++)
        acc = fmaf(__ldg(ar + h), sw[h * DD + d], acc);
    out[(size_t)r * DD + d] = acc;
}

// ---------------------------------------------------------------------------
extern "C" void kernel_launch(void* const* d_in, const int* in_sizes, int n_in,
                              void* d_out, int out_size)
{
    const float* x     = (const float*)d_in[0];
    const float* w_qkv = (const float*)d_in[1];
    const float* b_qkv = (const float*)d_in[2];
    const float* w_out = (const float*)d_in[3];
    const float* b_out = (const float*)d_in[4];
    float* out = (float*)d_out;

    float* gatt;
    cudaGetSymbolAddress((void**)&gatt, g_att);

    attn_poly_kernel<<<2 * NPAIR, 512>>>(x, w_qkv, b_qkv, gatt);
    out_kernel<<<512, 256>>>(gatt, w_out, b_out, out);
}

// round 12
// speedup vs baseline: 1.9323x; 1.9323x over previous
#include <cuda_runtime.h>
#include <cuda_bf16.h>
#include <cstdint>

// Problem constants (B=4, S=2048, D=16, HEADS=16, HEAD_SIZE=1)
#define BB   4
#define SS   2048
#define DD   16
#define NPAIR (BB * DD)          // 64 (b,h) pairs
#define HALF (SS / 2)            // 1024 rows per sub-block
#define NC   23                  // polynomial coefficients (degree 22)

// Scratch (allocation-free rule: __device__ global)
__device__ float g_att[BB * SS * DD];   // [b][s][h]

// ---------------------------------------------------------------------------
// Kernel 1: fused QKV + polynomial causal softmax-attention.
// grid 128 = 64 pairs x 2 sub-blocks (one block per SM), 512 threads.
// Scalar-head trick: e^{q k} = sum_p q^p/p! k^p is separable; causal attention
// = prefix sums of moments M_p[i] = sum_{j<=i} k_j^p (v_j).
// sub=0 scans rows [0,1024); sub=1 redundantly REDUCES first-half totals and
// scans rows [1024,2048). KEY (R12): first-half totals live ONLY in SMEM and
// enter through the warp-carry initialization (c = sbase[p]) — no pre[23]
// register array, no spills. Exclusive prefix via shfl_up(T,1); per-thread
// peak live ~T[23]+A[23]+scalars.
// ---------------------------------------------------------------------------
__global__ void __launch_bounds__(512) attn_poly_kernel(
    const float* __restrict__ x,      // [B, S, D]
    const float* __restrict__ w,      // [16, 48] row-major
    const float* __restrict__ bias,   // [48]
    float* __restrict__ gatt)         // [b][s][h]
{
    __shared__ float swq[DD], swk[DD], swv[DD];
    __shared__ float sb3[3];
    __shared__ float sWT[16][NC + 1];     // warp totals / pre-reduce scratch
    __shared__ float sWC[16][NC + 1];     // warp exclusive carries (incl. pre)
    __shared__ float sbase[NC + 1];       // first-half totals (sub=1)

    const float INVF[NC] = {
        1.0f, 1.0f, 0.5f, 1.6666667e-1f, 4.1666668e-2f, 8.3333338e-3f,
        1.3888889e-3f, 1.9841270e-4f, 2.4801588e-5f, 2.7557319e-6f,
        2.7557319e-7f, 2.5052108e-8f, 2.0876757e-9f, 1.6059044e-10f,
        1.1470746e-11f, 7.6471637e-13f, 4.7794773e-14f, 2.8114573e-15f,
        1.5619207e-16f, 8.2206352e-18f, 4.1103176e-19f, 1.9572941e-20f,
        8.8967914e-22f };

    int bid  = blockIdx.x;
    int pair = bid >> 1;
    int sub  = bid & 1;
    int b_idx = pair >> 4;
    int h_idx = pair & 15;
    int t = threadIdx.x, lane = t & 31, wrp = t >> 5;

    if (t < DD) {
        swq[t] = w[t * 48 + h_idx];
        swk[t] = w[t * 48 + 16 + h_idx];
        swv[t] = w[t * 48 + 32 + h_idx];
    }
    if (t < 3) sb3[t] = bias[t * 16 + h_idx];
    __syncthreads();

    float bq = sb3[0], bk = sb3[1], bv = sb3[2];
    const float4* xb = reinterpret_cast<const float4*>(x + (size_t)b_idx * SS * DD);

    // --- own rows: r0 = base + 2t, r1 = r0 + 1 ---
    int base = sub * HALF;
    int r0 = base + 2 * t, r1 = r0 + 1;

    float q0, k0, v0, q1, k1, v1;
    {
        float xr[DD];
        #pragma unroll
        for (int q4 = 0; q4 < 4; q4++) {
            float4 t4 = xb[r0 * 4 + q4];
            xr[q4*4+0]=t4.x; xr[q4*4+1]=t4.y; xr[q4*4+2]=t4.z; xr[q4*4+3]=t4.w;
        }
        q0 = bq; k0 = bk; v0 = bv;
        #pragma unroll
        for (int d = 0; d < DD; d++) {
            q0 = fmaf(xr[d], swq[d], q0);
            k0 = fmaf(xr[d], swk[d], k0);
            v0 = fmaf(xr[d], swv[d], v0);
        }
        #pragma unroll
        for (int q4 = 0; q4 < 4; q4++) {
            float4 t4 = xb[r1 * 4 + q4];
            xr[q4*4+0]=t4.x; xr[q4*4+1]=t4.y; xr[q4*4+2]=t4.z; xr[q4*4+3]=t4.w;
        }
        q1 = bq; k1 = bk; v1 = bv;
        #pragma unroll
        for (int d = 0; d < DD; d++) {
            q1 = fmaf(xr[d], swq[d], q1);
            k1 = fmaf(xr[d], swk[d], k1);
            v1 = fmaf(xr[d], swv[d], v1);
        }
    }

    // --- pre rows (first half) for sub=1: k,v only ---
    float pk0 = 0.f, pv0 = 0.f, pk1 = 0.f, pv1 = 0.f;
    if (sub) {
        int p0 = 2 * t, p1 = p0 + 1;
        float xr[DD];
        #pragma unroll
        for (int q4 = 0; q4 < 4; q4++) {
            float4 t4 = xb[p0 * 4 + q4];
            xr[q4*4+0]=t4.x; xr[q4*4+1]=t4.y; xr[q4*4+2]=t4.z; xr[q4*4+3]=t4.w;
        }
        pk0 = bk; pv0 = bv;
        #pragma unroll
        for (int d = 0; d < DD; d++) {
            pk0 = fmaf(xr[d], swk[d], pk0);
            pv0 = fmaf(xr[d], swv[d], pv0);
        }
        #pragma unroll
        for (int q4 = 0; q4 < 4; q4++) {
            float4 t4 = xb[p1 * 4 + q4];
            xr[q4*4+0]=t4.x; xr[q4*4+1]=t4.y; xr[q4*4+2]=t4.z; xr[q4*4+3]=t4.w;
        }
        pk1 = bk; pv1 = bv;
        #pragma unroll
        for (int d = 0; d < DD; d++) {
            pk1 = fmaf(xr[d], swk[d], pk1);
            pv1 = fmaf(xr[d], swv[d], pv1);
        }
    }

    float den0, den1;
    float* gout = gatt + (size_t)(b_idx * SS) * DD + h_idx;

    // ====================== two phases: 0 = den, 1 = num ======================
    #pragma unroll
    for (int phase = 0; phase < 2; phase++) {
        float m0 = phase ? v0 : 1.f;
        float m1 = phase ? v1 : 1.f;
        float pm0 = phase ? pv0 : 1.f;
        float pm1 = phase ? pv1 : 1.f;

        // --- pre-half total reduction into sbase (sub=1 only; smem-resident) ---
        if (sub) {
            float T[NC];        // reuse same register budget as the scan below
            {
                float kp = 1.f;
                #pragma unroll
                for (int p = 0; p < NC; p++) { T[p] = kp * pm0; kp *= pk0; }
                kp = 1.f;
                #pragma unroll
                for (int p = 0; p < NC; p++) { T[p] = fmaf(kp, pm1, T[p]); kp *= pk1; }
            }
            #pragma unroll
            for (int off = 16; off; off >>= 1)
                #pragma unroll
                for (int p = 0; p < NC; p++)
                    T[p] += __shfl_xor_sync(0xffffffffu, T[p], off);
            if (lane == 0)
                #pragma unroll
                for (int p = 0; p < NC; p++) sWT[wrp][p] = T[p];
            __syncthreads();
            if (wrp == 0 && lane < NC) {
                float s = 0.f;
                #pragma unroll
                for (int w16 = 0; w16 < 16; w16++) s += sWT[w16][lane];
                sbase[lane] = s;
            }
            __syncthreads();      // sbase ready; sWT free for reuse below
        }

        // --- serial moments of own 2 rows ---
        float T[NC];
        {
            float kp = 1.f;
            #pragma unroll
            for (int p = 0; p < NC; p++) { T[p] = kp * m0; kp *= k0; }
            kp = 1.f;
            #pragma unroll
            for (int p = 0; p < NC; p++) { T[p] = fmaf(kp, m1, T[p]); kp *= k1; }
        }

        // --- warp inclusive scan over lanes ---
        #pragma unroll
        for (int d = 1; d < 32; d <<= 1)
            #pragma unroll
            for (int p = 0; p < NC; p++) {
                float o = __shfl_up_sync(0xffffffffu, T[p], d);
                if (lane >= d) T[p] += o;
            }
        if (lane == 31)
            #pragma unroll
            for (int p = 0; p < NC; p++) sWT[wrp][p] = T[p];
        __syncthreads();

        // --- warp carries; pre-half totals enter HERE (smem -> smem) ---
        if (wrp == 0 && lane < NC) {
            float c = sub ? sbase[lane] : 0.f;
            #pragma unroll
            for (int w16 = 0; w16 < 16; w16++) {
                float tot = sWT[w16][lane];
                sWC[w16][lane] = c;
                c += tot;
            }
        }
        __syncthreads();

        // --- exclusive prefix for this thread, then include own rows + poly ---
        float A[NC];
        #pragma unroll
        for (int p = 0; p < NC; p++) {
            float o = __shfl_up_sync(0xffffffffu, T[p], 1);
            A[p] = sWC[wrp][p] + (lane ? o : 0.f);
        }
        __syncthreads();   // sWT/sWC/sbase reuse safety for next phase

        {
            float kp = 1.f;
            #pragma unroll
            for (int p = 0; p < NC; p++) { A[p] = fmaf(kp, m0, A[p]); kp *= k0; }
            float qp = 1.f, acc = 0.f;
            #pragma unroll
            for (int p = 0; p < NC; p++) { acc = fmaf(A[p] * INVF[p], qp, acc); qp *= q0; }
            if (phase == 0) den0 = acc;
            else            gout[(size_t)r0 * DD] = acc / den0;

            kp = 1.f;
            #pragma unroll
            for (int p = 0; p < NC; p++) { A[p] = fmaf(kp, m1, A[p]); kp *= k1; }
            qp = 1.f; acc = 0.f;
            #pragma unroll
            for (int p = 0; p < NC; p++) { acc = fmaf(A[p] * INVF[p], qp, acc); qp *= q1; }
            if (phase == 0) den1 = acc;
            else            gout[(size_t)r1 * DD] = acc / den1;
        }
    }
}

// ---------------------------------------------------------------------------
// Kernel 2: out = att @ w_out + b_out. Best measured config (R7, 4.19us):
// 512 blocks x 128 threads, 2 output cols per thread, float4 att reads.
// ---------------------------------------------------------------------------
__global__ void __launch_bounds__(128) out_kernel(
    const float* __restrict__ gatt,
    const float* __restrict__ w,    // [16,16] row-major
    const float* __restrict__ bias, // [16]
    float* __restrict__ out)
{
    __shared__ float sw[DD * DD];
    __shared__ float sb[DD];
    int t = threadIdx.x;
    sw[t]       = w[t];
    sw[t + 128] = w[t + 128];
    if (t < DD) sb[t] = bias[t];
    __syncthreads();

    int g  = blockIdx.x * 128 + t;        // 0 .. 65535
    int r  = g >> 3;                       // row 0..8191
    int d0 = (g & 7) * 2;                  // output col pair

    float a[DD];
    const float4* ap = reinterpret_cast<const float4*>(gatt + (size_t)r * DD);
    #pragma unroll
    for (int q4 = 0; q4 < 4; q4++) {
        float4 v4 = ap[q4];
        a[q4*4+0] = v4.x; a[q4*4+1] = v4.y; a[q4*4+2] = v4.z; a[q4*4+3] = v4.w;
    }

    float acc0 = sb[d0], acc1 = sb[d0 + 1];
    #pragma unroll
    for (int h = 0; h < DD; h++) {
        float2 w2 = *reinterpret_cast<const float2*>(&sw[h * DD + d0]);
        acc0 = fmaf(a[h], w2.x, acc0);
        acc1 = fmaf(a[h], w2.y, acc1);
    }
    *reinterpret_cast<float2*>(out + (size_t)r * DD + d0) = make_float2(acc0, acc1);
}

// ---------------------------------------------------------------------------
extern "C" void kernel_launch(void* const* d_in, const int* in_sizes, int n_in,
                              void* d_out, int out_size)
{
    const float* x     = (const float*)d_in[0];
    const float* w_qkv = (const float*)d_in[1];
    const float* b_qkv = (const float*)d_in[2];
    const float* w_out = (const float*)d_in[3];
    const float* b_out = (const float*)d_in[4];
    float* out = (float*)d_out;

    float* gatt;
    cudaGetSymbolAddress((void**)&gatt, g_att);

    attn_poly_kernel<<<2 * NPAIR, 512>>>(x, w_qkv, b_qkv, gatt);
    out_kernel<<<512, 128>>>(gatt, w_out, b_out, out);
}

// round 13
// speedup vs baseline: 2.1877x; 1.1322x over previous
#include <cuda_runtime.h>
#include <cuda_bf16.h>
#include <cstdint>

// Problem constants (B=4, S=2048, D=16, HEADS=16, HEAD_SIZE=1)
#define BB   4
#define SS   2048
#define DD   16
#define NPAIR (BB * DD)          // 64 (b,h) pairs
#define NC   23                  // polynomial terms (degree 22)

// Scratch (allocation-free rule: __device__ global)
__device__ float g_att[BB * SS * DD];   // [b][s][h]

// Immediate constants 1/(p+1) for the scaled q-power chain:
// qp_{p+1} = qp_p * q * INVP(p).  All folded as FP32 immediates.
#define INVP0  1.0f
#define INVP1  0.5f
#define INVP2  0.33333334f
#define INVP3  0.25f
#define INVP4  0.2f
#define INVP5  0.16666667f
#define INVP6  0.14285715f
#define INVP7  0.125f
#define INVP8  0.11111111f
#define INVP9  0.1f
#define INVP10 0.09090909f
#define INVP11 0.08333334f
#define INVP12 0.07692308f
#define INVP13 0.07142857f
#define INVP14 0.06666667f
#define INVP15 0.0625f
#define INVP16 0.05882353f
#define INVP17 0.055555556f
#define INVP18 0.052631579f
#define INVP19 0.05f
#define INVP20 0.047619048f
#define INVP21 0.045454547f
#define INVP22 0.043478262f

__device__ __forceinline__ float invp_const(int p) {
    // Fully unrolled callers make p compile-time; switch folds to an immediate.
    switch (p) {
        case 0:  return INVP0;  case 1:  return INVP1;  case 2:  return INVP2;
        case 3:  return INVP3;  case 4:  return INVP4;  case 5:  return INVP5;
        case 6:  return INVP6;  case 7:  return INVP7;  case 8:  return INVP8;
        case 9:  return INVP9;  case 10: return INVP10; case 11: return INVP11;
        case 12: return INVP12; case 13: return INVP13; case 14: return INVP14;
        case 15: return INVP15; case 16: return INVP16; case 17: return INVP17;
        case 18: return INVP18; case 19: return INVP19; case 20: return INVP20;
        case 21: return INVP21; default: return INVP22;
    }
}

// Evaluate acc = sum_p A[p] * q^p / p!  with immediates only (no mem access).
__device__ __forceinline__ float poly_eval(const float* A, float q) {
    float qp = 1.f, acc = 0.f;
    #pragma unroll
    for (int p = 0; p < NC; p++) {
        acc = fmaf(A[p], qp, acc);
        qp = qp * q * invp_const(p);       // q^{p+1}/(p+1)!
    }
    return acc;
}

// ---------------------------------------------------------------------------
// Kernel 1: fused QKV + polynomial causal softmax-attention (R8 structure).
// 64 blocks (one per (b,h) pair) x 512 threads, 4 consecutive rows/thread.
// e^{qk} = sum_p q^p/p! k^p (separable) -> causal attention = prefix sums of
// moment series M_p[i] = sum_{j<=i} k_j^p (v_j). Two register-light phases
// (den then num): serial moments (4 rows) -> warp shfl-scan -> warp carries
// -> per-row poly eval. 1/p! lives in the q-power chain as immediates.
// ---------------------------------------------------------------------------
__global__ void __launch_bounds__(512) attn_poly_kernel(
    const float* __restrict__ x,      // [B, S, D]
    const float* __restrict__ w,      // [16, 48] row-major
    const float* __restrict__ bias,   // [48]
    float* __restrict__ gatt)         // [b][s][h]
{
    __shared__ float sk[SS], sv[SS], sq[SS], sden[SS];   // 32KB
    __shared__ float sWT[16][NC + 1];
    __shared__ float sWC[16][NC + 1];
    __shared__ float swq[DD], swk[DD], swv[DD];
    __shared__ float sbias[3];

    int pair = blockIdx.x;
    int b_idx = pair >> 4;
    int h_idx = pair & 15;
    int t = threadIdx.x, lane = t & 31, wrp = t >> 5;

    if (t < DD) {
        swq[t] = w[t * 48 + h_idx];
        swk[t] = w[t * 48 + 16 + h_idx];
        swv[t] = w[t * 48 + 32 + h_idx];
    }
    if (t < 3) sbias[t] = bias[t * 16 + h_idx];
    __syncthreads();

    float bq = sbias[0], bk = sbias[1], bv = sbias[2];

    // --- prologue: q/k/v for all 2048 rows of this pair ---
    const float4* xb = reinterpret_cast<const float4*>(x + (size_t)b_idx * SS * DD);
    #pragma unroll
    for (int it = 0; it < SS / 512; it++) {
        int j = t + 512 * it;
        float xr[DD];
        #pragma unroll
        for (int q4 = 0; q4 < 4; q4++) {
            float4 v4 = xb[j * 4 + q4];
            xr[q4*4+0] = v4.x; xr[q4*4+1] = v4.y;
            xr[q4*4+2] = v4.z; xr[q4*4+3] = v4.w;
        }
        float aq = bq, ak = bk, av = bv;
        #pragma unroll
        for (int d = 0; d < DD; d++) {
            float xd = xr[d];
            aq = fmaf(xd, swq[d], aq);
            ak = fmaf(xd, swk[d], ak);
            av = fmaf(xd, swv[d], av);
        }
        sq[j] = aq; sk[j] = ak; sv[j] = av;
    }
    __syncthreads();

    const int J0 = t * 4;   // this thread's 4 consecutive rows

    // =================== PHASE 1: DEN (moments of k^p) ===================
    {
        float T[NC];
        #pragma unroll
        for (int p = 0; p < NC; p++) T[p] = 0.f;
        #pragma unroll
        for (int jj = 0; jj < 4; jj++) {
            float kj = sk[J0 + jj];
            float kp = 1.f;
            #pragma unroll
            for (int p = 0; p < NC; p++) { T[p] += kp; kp *= kj; }
        }
        float OT[NC];
        #pragma unroll
        for (int p = 0; p < NC; p++) OT[p] = T[p];
        #pragma unroll
        for (int d = 1; d < 32; d <<= 1) {
            #pragma unroll
            for (int p = 0; p < NC; p++) {
                float o = __shfl_up_sync(0xffffffffu, T[p], d);
                if (lane >= d) T[p] += o;
            }
        }
        if (lane == 31) {
            #pragma unroll
            for (int p = 0; p < NC; p++) sWT[wrp][p] = T[p];
        }
        __syncthreads();
        if (wrp == 0 && lane < NC) {
            float c = 0.f;
            #pragma unroll
            for (int w16 = 0; w16 < 16; w16++) {
                float tot = sWT[w16][lane];
                sWC[w16][lane] = c;
                c += tot;
            }
        }
        __syncthreads();
        float A[NC];
        #pragma unroll
        for (int p = 0; p < NC; p++) A[p] = sWC[wrp][p] + (T[p] - OT[p]);
        #pragma unroll
        for (int jj = 0; jj < 4; jj++) {
            int j = J0 + jj;
            float kj = sk[j];
            float kp = 1.f;
            #pragma unroll
            for (int p = 0; p < NC; p++) { A[p] += kp; kp *= kj; }
            sden[j] = poly_eval(A, sq[j]);
        }
    }
    __syncthreads();

    // =================== PHASE 2: NUM (moments of k^p * v) ===================
    {
        float T[NC];
        #pragma unroll
        for (int p = 0; p < NC; p++) T[p] = 0.f;
        #pragma unroll
        for (int jj = 0; jj < 4; jj++) {
            float kj = sk[J0 + jj];
            float vj = sv[J0 + jj];
            float kp = 1.f;
            #pragma unroll
            for (int p = 0; p < NC; p++) { T[p] = fmaf(kp, vj, T[p]); kp *= kj; }
        }
        float OT[NC];
        #pragma unroll
        for (int p = 0; p < NC; p++) OT[p] = T[p];
        #pragma unroll
        for (int d = 1; d < 32; d <<= 1) {
            #pragma unroll
            for (int p = 0; p < NC; p++) {
                float o = __shfl_up_sync(0xffffffffu, T[p], d);
                if (lane >= d) T[p] += o;
            }
        }
        if (lane == 31) {
            #pragma unroll
            for (int p = 0; p < NC; p++) sWT[wrp][p] = T[p];
        }
        __syncthreads();
        if (wrp == 0 && lane < NC) {
            float c = 0.f;
            #pragma unroll
            for (int w16 = 0; w16 < 16; w16++) {
                float tot = sWT[w16][lane];
                sWC[w16][lane] = c;
                c += tot;
            }
        }
        __syncthreads();
        float A[NC];
        #pragma unroll
        for (int p = 0; p < NC; p++) A[p] = sWC[wrp][p] + (T[p] - OT[p]);

        float* gout = gatt + (size_t)(b_idx * SS) * DD + h_idx;
        #pragma unroll
        for (int jj = 0; jj < 4; jj++) {
            int j = J0 + jj;
            float kj = sk[j];
            float vj = sv[j];
            float kp = 1.f;
            #pragma unroll
            for (int p = 0; p < NC; p++) { A[p] = fmaf(kp, vj, A[p]); kp *= kj; }
            float acc = poly_eval(A, sq[j]);
            gout[(size_t)j * DD] = acc / sden[j];
        }
    }
}

// ---------------------------------------------------------------------------
// Kernel 2: out = att @ w_out + b_out. 512 blocks x 128 threads, 2 output
// cols per thread, float4 att reads (best measured config: 4.19us).
// ---------------------------------------------------------------------------
__global__ void __launch_bounds__(128) out_kernel(
    const float* __restrict__ gatt,
    const float* __restrict__ w,    // [16,16] row-major
    const float* __restrict__ bias, // [16]
    float* __restrict__ out)
{
    __shared__ float sw[DD * DD];
    __shared__ float sb[DD];
    int t = threadIdx.x;
    sw[t]       = w[t];
    sw[t + 128] = w[t + 128];
    if (t < DD) sb[t] = bias[t];
    __syncthreads();

    int g  = blockIdx.x * 128 + t;        // 0 .. 65535
    int r  = g >> 3;                       // row 0..8191
    int d0 = (g & 7) * 2;                  // output col pair

    float a[DD];
    const float4* ap = reinterpret_cast<const float4*>(gatt + (size_t)r * DD);
    #pragma unroll
    for (int q4 = 0; q4 < 4; q4++) {
        float4 v4 = ap[q4];
        a[q4*4+0] = v4.x; a[q4*4+1] = v4.y; a[q4*4+2] = v4.z; a[q4*4+3] = v4.w;
    }

    float acc0 = sb[d0], acc1 = sb[d0 + 1];
    #pragma unroll
    for (int h = 0; h < DD; h++) {
        float2 w2 = *reinterpret_cast<const float2*>(&sw[h * DD + d0]);
        acc0 = fmaf(a[h], w2.x, acc0);
        acc1 = fmaf(a[h], w2.y, acc1);
    }
    *reinterpret_cast<float2*>(out + (size_t)r * DD + d0) = make_float2(acc0, acc1);
}

// ---------------------------------------------------------------------------
extern "C" void kernel_launch(void* const* d_in, const int* in_sizes, int n_in,
                              void* d_out, int out_size)
{
    const float* x     = (const float*)d_in[0];
    const float* w_qkv = (const float*)d_in[1];
    const float* b_qkv = (const float*)d_in[2];
    const float* w_out = (const float*)d_in[3];
    const float* b_out = (const float*)d_in[4];
    float* out = (float*)d_out;

    float* gatt;
    cudaGetSymbolAddress((void**)&gatt, g_att);

    attn_poly_kernel<<<NPAIR, 512>>>(x, w_qkv, b_qkv, gatt);
    out_kernel<<<512, 128>>>(gatt, w_out, b_out, out);
}